// round 6
// baseline (speedup 1.0000x reference)
#include <cuda_runtime.h>
#include <cstdint>

#define HH 128
#define WW 192
#define CC_TOT 256
#define BB 8
#define TILE_W 32
#define TILE_H 16
#define HALO_W 40
#define HALO_H 24
#define CHUNK 4
#define NCHUNK (CC_TOT / CHUNK)
#define NT 384
#define PLANE ((size_t)HH * WW)

#define PSEC (HALO_H * HALO_W * 4)                    // 3840
#define PREV_BUF (CHUNK * PSEC)                       // 15360
#define CURR_BUF (CHUNK * TILE_H * TILE_W * 4)        // 8192
#define SM_PREV 0
#define SM_CURR (3 * PREV_BUF)                        // 46080
#define SM_SSP  (SM_CURR + 3 * CURR_BUF)              // 70656
#define SMEM_BYTES (SM_SSP + HALO_H * HALO_W * 4)     // 74496 -> 2 CTAs/SM

typedef unsigned long long u64;

__device__ __forceinline__ void F2(u64 &d, u64 a, u64 b) {
    asm("fma.rn.f32x2 %0, %1, %2, %0;" : "+l"(d) : "l"(a), "l"(b));
}
__device__ __forceinline__ u64 M2(u64 a, u64 b) {
    u64 d; asm("mul.rn.f32x2 %0, %1, %2;" : "=l"(d) : "l"(a), "l"(b)); return d;
}
__device__ __forceinline__ u64 PK(unsigned a, unsigned b) {
    u64 d; asm("mov.b64 %0, {%1, %2};" : "=l"(d) : "r"(a), "r"(b)); return d;
}
__device__ __forceinline__ unsigned LOW(u64 a) {
    unsigned l, h; asm("mov.b64 {%0, %1}, %2;" : "=r"(l), "=r"(h) : "l"(a)); return l;
}
__device__ __forceinline__ unsigned HIW(u64 a) {
    unsigned l, h; asm("mov.b64 {%0, %1}, %2;" : "=r"(l), "=r"(h) : "l"(a)); return h;
}
__device__ __forceinline__ float FL(u64 a) { return __uint_as_float(LOW(a)); }
__device__ __forceinline__ float FH(u64 a) { return __uint_as_float(HIW(a)); }
__device__ __forceinline__ void cp16(uint32_t dst, const void* src, int szbytes) {
    asm volatile("cp.async.cg.shared.global [%0], [%1], 16, %2;\n"
                 :: "r"(dst), "l"(src), "r"(szbytes) : "memory");
}
__device__ __forceinline__ ulonglong2 LD2(const void* p) {
    return *reinterpret_cast<const ulonglong2*>(p);
}
__device__ __forceinline__ u64 LD1(const void* p) {
    return *reinterpret_cast<const u64*>(p);
}

__global__ void __launch_bounds__(NT, 2)
corr_kernel(const float* __restrict__ curr, const float* __restrict__ prev,
            float* __restrict__ out)
{
    extern __shared__ char smem[];

    const int tid = threadIdx.x;
    const int wg  = tid >> 7;          // warpgroup: 0,1,2
    const int wt  = tid & 127;
    const int g   = wt & 7;
    const int tx4 = g * 4;
    const int ty  = wt >> 3;
    const int x0  = blockIdx.x * TILE_W;
    const int y0  = blockIdx.y * TILE_H;
    const int bb  = blockIdx.z;

    const char* currB = (const char*)(curr + (size_t)bb * CC_TOT * PLANE);
    const char* prevB = (const char*)(prev + (size_t)bb * CC_TOT * PLANE);
    const uint32_t smA = (uint32_t)__cvta_generic_to_shared(smem);

    // ---- staging precompute ----
    // prev: 240 f4 slots per cc, thread tid<240 owns slot tid
    const int psy = tid / 10, psx = tid - psy * 10;
    const int pgy = y0 - 4 + psy, pgx = x0 - 4 + psx * 4;
    const bool doP = (tid < 240);
    const bool pok = doP && ((unsigned)pgy < HH) && ((unsigned)pgx < WW);
    const int pOff = pok ? (pgy * WW + pgx) * 4 : 0;
    const int psz  = pok ? 16 : 0;
    // curr: 128 f4 slots, staged by threads 256..383
    const bool doC = (tid >= 256);
    const int cslot = tid - 256;
    const int cOff = doC ? (((y0 + (cslot >> 3)) * WW) + x0 + (cslot & 7) * 4) * 4 : 0;

    const uint32_t sOff = (uint32_t)(doP ? tid : 0) * 16;

    // ---- accumulators ----
    // wg0: p0..9 = dy-4 (o0..4), dy-2 (o5..9)
    // wg1: p0..2 = dy-1 (o10..12); p3..9 = dy0 (o13..19); p10..12 = dy+1 (o20..22)
    // wg2: p0..4 = dy+2 (o23..27); p5..9 = dy+4 (o28..32)
    u64 pL[13], pH[13];
    #pragma unroll
    for (int o = 0; o < 13; o++) { pL[o] = 0ull; pH[o] = 0ull; }
    u64 ssqL = 0ull, ssqH = 0ull;
    u64 sqL = 0ull, sqH = 0ull;

    auto issue = [&](const char* srcP, const char* srcC, uint32_t dP, uint32_t dC) {
        #pragma unroll
        for (int cc = 0; cc < CHUNK; cc++) {
            const size_t so = (size_t)cc * PLANE * 4;
            if (doP) cp16(dP + cc * PSEC + tid * 16, srcP + so + pOff, psz);
            if (doC) cp16(dC + cc * 2048 + cslot * 16, srcC + so + cOff, 16);
        }
        asm volatile("cp.async.commit_group;\n" ::: "memory");
    };

    issue(prevB, currB, smA + SM_PREV, smA + SM_CURR);
    issue(prevB + (size_t)CHUNK * PLANE * 4, currB + (size_t)CHUNK * PLANE * 4,
          smA + SM_PREV + PREV_BUF, smA + SM_CURR + CURR_BUF);

    const char* srcPs = prevB + (size_t)2 * CHUNK * PLANE * 4;
    const char* srcCs = currB + (size_t)2 * CHUNK * PLANE * 4;
    int bC = 0, bS = 2;

    const int rowOff = (ty * HALO_W + tx4) * 4;
    const int cvOff  = (ty * TILE_W + tx4) * 4;

#define PROW(O, Q0, Q1, Q2) do { \
    F2(pL[O + 0], cvL, (Q0).x); F2(pH[O + 0], cvH, (Q0).y); \
    F2(pL[O + 1], cvL, (Q0).y); F2(pH[O + 1], cvH, (Q1).x); \
    F2(pL[O + 2], cvL, (Q1).x); F2(pH[O + 2], cvH, (Q1).y); \
    F2(pL[O + 3], cvL, (Q1).y); F2(pH[O + 3], cvH, (Q2).x); \
    F2(pL[O + 4], cvL, (Q2).x); F2(pH[O + 4], cvH, (Q2).y); } while (0)

#define PMID(O, A1, Q1, A4) do { \
    const u64 P34 = PK(HIW(A1), LOW((Q1).x)); \
    const u64 P56 = PK(HIW((Q1).x), LOW((Q1).y)); \
    const u64 P78 = PK(HIW((Q1).y), LOW(A4)); \
    F2(pL[O + 0], cvL, P34);    F2(pH[O + 0], cvH, P56); \
    F2(pL[O + 1], cvL, (Q1).x); F2(pH[O + 1], cvH, (Q1).y); \
    F2(pL[O + 2], cvL, P56);    F2(pH[O + 2], cvH, P78); } while (0)

    #pragma unroll 1
    for (int k = 0; k < NCHUNK; k++) {
        if (k < NCHUNK - 1) asm volatile("cp.async.wait_group 1;\n" ::: "memory");
        else                asm volatile("cp.async.wait_group 0;\n" ::: "memory");
        __syncthreads();

        if (k < NCHUNK - 2) {
            issue(srcPs, srcCs, smA + SM_PREV + bS * PREV_BUF, smA + SM_CURR + bS * CURR_BUF);
            srcPs += (size_t)CHUNK * PLANE * 4;
            srcCs += (size_t)CHUNK * PLANE * 4;
            bS = (bS == 2) ? 0 : bS + 1;
        }

        const char* pbuf = smem + SM_PREV + bC * PREV_BUF;
        const char* cbuf = smem + SM_CURR + bC * CURR_BUF;

        if (wg == 0) {
            #pragma unroll
            for (int cc = 0; cc < CHUNK; cc++) {
                const char* secB = pbuf + cc * PSEC;
                const char* rowB = secB + rowOff;
                const ulonglong2 CV = LD2(cbuf + cc * 2048 + cvOff);
                const ulonglong2 SQ = LD2(secB + sOff);
                const u64 cvL = CV.x, cvH = CV.y;
                F2(ssqL, cvL, cvL); F2(ssqH, cvH, cvH);
                F2(sqL, SQ.x, SQ.x); F2(sqH, SQ.y, SQ.y);
                {   // dy=-4 : p0..4
                    const ulonglong2 q0 = LD2(rowB), q1 = LD2(rowB + 16), q2 = LD2(rowB + 32);
                    PROW(0, q0, q1, q2);
                }
                {   // dy=-2 : p5..9
                    const ulonglong2 q0 = LD2(rowB + 320), q1 = LD2(rowB + 336), q2 = LD2(rowB + 352);
                    PROW(5, q0, q1, q2);
                }
            }
        } else if (wg == 1) {
            #pragma unroll
            for (int cc = 0; cc < CHUNK; cc++) {
                const char* secB = pbuf + cc * PSEC;
                const char* rowB = secB + rowOff;
                const ulonglong2 CV = LD2(cbuf + cc * 2048 + cvOff);
                const u64 cvL = CV.x, cvH = CV.y;
                F2(ssqL, cvL, cvL); F2(ssqH, cvH, cvH);
                if (tid < 240) {
                    const ulonglong2 SQ = LD2(secB + sOff);
                    F2(sqL, SQ.x, SQ.x); F2(sqH, SQ.y, SQ.y);
                }
                {   // dy=-1 : p0..2
                    const u64 a1 = LD1(rowB + 488);
                    const ulonglong2 q1 = LD2(rowB + 496);
                    const u64 a4 = LD1(rowB + 512);
                    PMID(0, a1, q1, a4);
                }
                {   // dy=0 : p3..9 (dx -4,-2,-1,0,1,2,4)
                    const ulonglong2 q0 = LD2(rowB + 640), q1 = LD2(rowB + 656), q2 = LD2(rowB + 672);
                    F2(pL[3], cvL, q0.x); F2(pH[3], cvH, q0.y);
                    F2(pL[4], cvL, q0.y); F2(pH[4], cvH, q1.x);
                    const u64 P34 = PK(HIW(q0.y), LOW(q1.x));
                    const u64 P56 = PK(HIW(q1.x), LOW(q1.y));
                    const u64 P78 = PK(HIW(q1.y), LOW(q2.x));
                    F2(pL[5], cvL, P34);  F2(pH[5], cvH, P56);
                    F2(pL[6], cvL, q1.x); F2(pH[6], cvH, q1.y);
                    F2(pL[7], cvL, P56);  F2(pH[7], cvH, P78);
                    F2(pL[8], cvL, q1.y); F2(pH[8], cvH, q2.x);
                    F2(pL[9], cvL, q2.x); F2(pH[9], cvH, q2.y);
                }
                {   // dy=+1 : p10..12
                    const u64 a1 = LD1(rowB + 808);
                    const ulonglong2 q1 = LD2(rowB + 816);
                    const u64 a4 = LD1(rowB + 832);
                    PMID(10, a1, q1, a4);
                }
            }
        } else {
            #pragma unroll
            for (int cc = 0; cc < CHUNK; cc++) {
                const char* secB = pbuf + cc * PSEC;
                const char* rowB = secB + rowOff;
                const ulonglong2 CV = LD2(cbuf + cc * 2048 + cvOff);
                const u64 cvL = CV.x, cvH = CV.y;
                F2(ssqL, cvL, cvL); F2(ssqH, cvH, cvH);
                {   // dy=+2 : p0..4
                    const ulonglong2 q0 = LD2(rowB + 960), q1 = LD2(rowB + 976), q2 = LD2(rowB + 992);
                    PROW(0, q0, q1, q2);
                }
                {   // dy=+4 : p5..9
                    const ulonglong2 q0 = LD2(rowB + 1280), q1 = LD2(rowB + 1296), q2 = LD2(rowB + 1312);
                    PROW(5, q0, q1, q2);
                }
            }
        }
        bC = (bC == 2) ? 0 : bC + 1;
    }

    // ---- epilogue: inverse prev norms ----
    if (tid < 240) {
        float* ssp = (float*)(smem + SM_SSP);
        const float a = FL(sqL), b = FH(sqL), c = FL(sqH), d = FH(sqH);
        float4 r;
        r.x = a > 0.f ? rsqrtf(a) : 0.f;
        r.y = b > 0.f ? rsqrtf(b) : 0.f;
        r.z = c > 0.f ? rsqrtf(c) : 0.f;
        r.w = d > 0.f ? rsqrtf(d) : 0.f;
        ((float4*)ssp)[tid] = r;
    }
    __syncthreads();

    const float ic0 = rsqrtf(FL(ssqL));
    const float ic1 = rsqrtf(FH(ssqL));
    const float ic2 = rsqrtf(FL(ssqH));
    const float ic3 = rsqrtf(FH(ssqH));
    const u64 invL = PK(__float_as_uint(ic0), __float_as_uint(ic1));
    const u64 invH = PK(__float_as_uint(ic2), __float_as_uint(ic3));

    const char* srow = smem + SM_SSP + rowOff;
    char* outPix = (char*)(out + ((size_t)bb * 33 * HH + (y0 + ty)) * WW + x0 + tx4);

#define ESTP(OPL, PI, BL, BH) do { \
    ulonglong2 _r; \
    _r.x = M2(M2(pL[PI], invL), (BL)); \
    _r.y = M2(M2(pH[PI], invH), (BH)); \
    *(ulonglong2*)(outPix + (size_t)(OPL) * (PLANE * 4)) = _r; } while (0)

#define EROWF(ROFF, OPL, PI) do { \
    const ulonglong2 q0 = LD2(srow + (ROFF)), q1 = LD2(srow + (ROFF) + 16), \
                     q2 = LD2(srow + (ROFF) + 32); \
    ESTP(OPL + 0, PI + 0, q0.x, q0.y); \
    ESTP(OPL + 1, PI + 1, q0.y, q1.x); \
    ESTP(OPL + 2, PI + 2, q1.x, q1.y); \
    ESTP(OPL + 3, PI + 3, q1.y, q2.x); \
    ESTP(OPL + 4, PI + 4, q2.x, q2.y); } while (0)

#define EMID(ROFF, OPL, PI) do { \
    const u64 a1 = LD1(srow + (ROFF) - 8); \
    const ulonglong2 q1 = LD2(srow + (ROFF)); \
    const u64 a4 = LD1(srow + (ROFF) + 16); \
    const u64 P34 = PK(HIW(a1), LOW(q1.x)); \
    const u64 P56 = PK(HIW(q1.x), LOW(q1.y)); \
    const u64 P78 = PK(HIW(q1.y), LOW(a4)); \
    ESTP(OPL + 0, PI + 0, P34, P56); \
    ESTP(OPL + 1, PI + 1, q1.x, q1.y); \
    ESTP(OPL + 2, PI + 2, P56, P78); } while (0)

    if (wg == 0) {
        EROWF(0, 0, 0);       // dy=-4: o0..4
        EROWF(320, 5, 5);     // dy=-2: o5..9
    } else if (wg == 1) {
        EMID(496, 10, 0);     // dy=-1: o10..12
        {                     // dy=0: o13..19
            const ulonglong2 q0 = LD2(srow + 640), q1 = LD2(srow + 656), q2 = LD2(srow + 672);
            ESTP(13, 3, q0.x, q0.y);
            ESTP(14, 4, q0.y, q1.x);
            const u64 P34 = PK(HIW(q0.y), LOW(q1.x));
            const u64 P56 = PK(HIW(q1.x), LOW(q1.y));
            const u64 P78 = PK(HIW(q1.y), LOW(q2.x));
            ESTP(15, 5, P34, P56);
            ESTP(16, 6, q1.x, q1.y);
            ESTP(17, 7, P56, P78);
            ESTP(18, 8, q1.y, q2.x);
            ESTP(19, 9, q2.x, q2.y);
        }
        EMID(816, 20, 10);    // dy=+1: o20..22
    } else {
        EROWF(960, 23, 0);    // dy=+2: o23..27
        EROWF(1280, 28, 5);   // dy=+4: o28..32
    }
}

extern "C" void kernel_launch(void* const* d_in, const int* in_sizes, int n_in,
                              void* d_out, int out_size)
{
    const float* curr = (const float*)d_in[0];
    const float* prev = (const float*)d_in[1];
    float* out = (float*)d_out;

    cudaFuncSetAttribute(corr_kernel, cudaFuncAttributeMaxDynamicSharedMemorySize, SMEM_BYTES);

    dim3 grid(WW / TILE_W, HH / TILE_H, BB);   // 6 x 8 x 8 = 384 blocks
    corr_kernel<<<grid, NT, SMEM_BYTES>>>(curr, prev, out);
}

// round 7
// speedup vs baseline: 1.1591x; 1.1591x over previous
#include <cuda_runtime.h>
#include <cstdint>

#define HH 128
#define WW 192
#define CC_TOT 256
#define BB 8
#define TILE_W 32
#define TILE_H 16
#define HALO_W 40
#define HALO_H 24
#define CHUNK 4
#define NCHUNK (CC_TOT / CHUNK)
#define NT 256
#define PLANE ((size_t)HH * WW)

#define PSEC (HALO_H * HALO_W * 4)                    // 3840
#define PREV_BUF (CHUNK * PSEC)                       // 15360
#define CURR_BUF (CHUNK * TILE_H * TILE_W * 4)        // 8192
#define SM_PREV 0
#define SM_CURR (3 * PREV_BUF)                        // 46080
#define SM_SSP  (SM_CURR + 3 * CURR_BUF)              // 70656
#define SMEM_BYTES (SM_SSP + HALO_H * HALO_W * 4)     // 74496 -> 2 CTAs/SM

typedef unsigned long long u64;

__device__ __forceinline__ void F2(u64 &d, u64 a, u64 b) {
    asm("fma.rn.f32x2 %0, %1, %2, %0;" : "+l"(d) : "l"(a), "l"(b));
}
__device__ __forceinline__ u64 M2(u64 a, u64 b) {
    u64 d; asm("mul.rn.f32x2 %0, %1, %2;" : "=l"(d) : "l"(a), "l"(b)); return d;
}
__device__ __forceinline__ u64 PK(unsigned a, unsigned b) {
    u64 d; asm("mov.b64 %0, {%1, %2};" : "=l"(d) : "r"(a), "r"(b)); return d;
}
__device__ __forceinline__ unsigned LOW(u64 a) {
    unsigned l, h; asm("mov.b64 {%0, %1}, %2;" : "=r"(l), "=r"(h) : "l"(a)); return l;
}
__device__ __forceinline__ unsigned HIW(u64 a) {
    unsigned l, h; asm("mov.b64 {%0, %1}, %2;" : "=r"(l), "=r"(h) : "l"(a)); return h;
}
__device__ __forceinline__ float FL(u64 a) { return __uint_as_float(LOW(a)); }
__device__ __forceinline__ float FH(u64 a) { return __uint_as_float(HIW(a)); }
__device__ __forceinline__ void cp16(uint32_t dst, const void* src, int szbytes) {
    asm volatile("cp.async.cg.shared.global [%0], [%1], 16, %2;\n"
                 :: "r"(dst), "l"(src), "r"(szbytes) : "memory");
}
__device__ __forceinline__ ulonglong2 LD2(const void* p) {
    return *reinterpret_cast<const ulonglong2*>(p);
}
__device__ __forceinline__ u64 LD1(const void* p) {
    return *reinterpret_cast<const u64*>(p);
}

__global__ void __launch_bounds__(NT, 2)
corr_kernel(const float* __restrict__ curr, const float* __restrict__ prev,
            float* __restrict__ out)
{
    extern __shared__ char smem[];

    const int tid = threadIdx.x;
    const int wg  = tid >> 7;          // 0 or 1
    const int wt  = tid & 127;
    const int g   = wt & 7;
    const int tx4 = g * 4;
    const int ty  = wt >> 3;
    const int x0  = blockIdx.x * TILE_W;
    const int y0  = blockIdx.y * TILE_H;
    const int bb  = blockIdx.z;

    const char* currB = (const char*)(curr + (size_t)bb * CC_TOT * PLANE);
    const char* prevB = (const char*)(prev + (size_t)bb * CC_TOT * PLANE);
    const uint32_t smA = (uint32_t)__cvta_generic_to_shared(smem);

    // ---- staging precompute ----
    const int psy = tid / 10, psx = tid - psy * 10;
    const int pgy = y0 - 4 + psy, pgx = x0 - 4 + psx * 4;
    const bool doP = (tid < 240);
    const bool pok = doP && ((unsigned)pgy < HH) && ((unsigned)pgx < WW);
    const int pOff = pok ? (pgy * WW + pgx) * 4 : 0;
    const int psz  = pok ? 16 : 0;
    const bool doC = (tid >= 128);
    const int cslot = tid - 128;
    const int cOff = doC ? (((y0 + (cslot >> 3)) * WW) + x0 + (cslot & 7) * 4) * 4 : 0;

    // ---- boundary-sq fallback: 112 slots split 56/56 across warpgroups ----
    const bool doFB = (wt < 56);
    int fbSlot = 0;
    {
        const int j = wg * 56 + wt;
        if (j < 40)      fbSlot = j;                     // rows 0..3
        else if (j < 80) fbSlot = 200 + (j - 40);        // rows 20..23
        else { const int i = j - 80; fbSlot = (4 + (i >> 1)) * 10 + ((i & 1) ? 9 : 0); }
    }
    const uint32_t fbOff = (uint32_t)fbSlot * 16;

    // ---- accumulators ----
    // wg0: p0..4=dy-4(o0..4), p5..9=dy-2(o5..9), p10..16=dy0(o13..19)
    // wg1: p0..2=dy-1(o10..12), p3..5=dy+1(o20..22), p6..10=dy+2(o23..27), p11..15=dy+4(o28..32)
    u64 pL[17], pH[17];
    #pragma unroll
    for (int o = 0; o < 17; o++) { pL[o] = 0ull; pH[o] = 0ull; }
    u64 ssqL = 0ull, ssqH = 0ull;     // curr sum-of-squares
    u64 sqML = 0ull, sqMH = 0ull;     // wg0: own prev pixel sq (from dy0 q1)
    u64 sqFL = 0ull, sqFH = 0ull;     // fallback boundary sq

    auto issue = [&](const char* srcP, const char* srcC, uint32_t dP, uint32_t dC) {
        #pragma unroll
        for (int cc = 0; cc < CHUNK; cc++) {
            const size_t so = (size_t)cc * PLANE * 4;
            if (doP) cp16(dP + cc * PSEC + tid * 16, srcP + so + pOff, psz);
            if (doC) cp16(dC + cc * 2048 + cslot * 16, srcC + so + cOff, 16);
        }
        asm volatile("cp.async.commit_group;\n" ::: "memory");
    };

    issue(prevB, currB, smA + SM_PREV, smA + SM_CURR);
    issue(prevB + (size_t)CHUNK * PLANE * 4, currB + (size_t)CHUNK * PLANE * 4,
          smA + SM_PREV + PREV_BUF, smA + SM_CURR + CURR_BUF);

    const char* srcPs = prevB + (size_t)2 * CHUNK * PLANE * 4;
    const char* srcCs = currB + (size_t)2 * CHUNK * PLANE * 4;
    int bC = 0, bS = 2;

    const int rowOff = (ty * HALO_W + tx4) * 4;
    const int cvOff  = (ty * TILE_W + tx4) * 4;

#define PROW(O, Q0, Q1, Q2) do { \
    F2(pL[O + 0], cvL, (Q0).x); F2(pH[O + 0], cvH, (Q0).y); \
    F2(pL[O + 1], cvL, (Q0).y); F2(pH[O + 1], cvH, (Q1).x); \
    F2(pL[O + 2], cvL, (Q1).x); F2(pH[O + 2], cvH, (Q1).y); \
    F2(pL[O + 3], cvL, (Q1).y); F2(pH[O + 3], cvH, (Q2).x); \
    F2(pL[O + 4], cvL, (Q2).x); F2(pH[O + 4], cvH, (Q2).y); } while (0)

#define PMID(O, A1, Q1, A4) do { \
    const u64 P34 = PK(HIW(A1), LOW((Q1).x)); \
    const u64 P56 = PK(HIW((Q1).x), LOW((Q1).y)); \
    const u64 P78 = PK(HIW((Q1).y), LOW(A4)); \
    F2(pL[O + 0], cvL, P34);    F2(pH[O + 0], cvH, P56); \
    F2(pL[O + 1], cvL, (Q1).x); F2(pH[O + 1], cvH, (Q1).y); \
    F2(pL[O + 2], cvL, P56);    F2(pH[O + 2], cvH, P78); } while (0)

    #pragma unroll 1
    for (int k = 0; k < NCHUNK; k++) {
        if (k < NCHUNK - 1) asm volatile("cp.async.wait_group 1;\n" ::: "memory");
        else                asm volatile("cp.async.wait_group 0;\n" ::: "memory");
        __syncthreads();

        if (k < NCHUNK - 2) {
            issue(srcPs, srcCs, smA + SM_PREV + bS * PREV_BUF, smA + SM_CURR + bS * CURR_BUF);
            srcPs += (size_t)CHUNK * PLANE * 4;
            srcCs += (size_t)CHUNK * PLANE * 4;
            bS = (bS == 2) ? 0 : bS + 1;
        }

        const char* pbuf = smem + SM_PREV + bC * PREV_BUF;
        const char* cbuf = smem + SM_CURR + bC * CURR_BUF;

        if (wg == 0) {
            #pragma unroll
            for (int cc = 0; cc < CHUNK; cc++) {
                const char* secB = pbuf + cc * PSEC;
                const char* rowB = secB + rowOff;
                const ulonglong2 CV = LD2(cbuf + cc * 2048 + cvOff);
                const u64 cvL = CV.x, cvH = CV.y;
                F2(ssqL, cvL, cvL); F2(ssqH, cvH, cvH);
                if (doFB) {
                    const ulonglong2 SQ = LD2(secB + fbOff);
                    F2(sqFL, SQ.x, SQ.x); F2(sqFH, SQ.y, SQ.y);
                }
                {   // dy=-4 : p0..4
                    const ulonglong2 q0 = LD2(rowB), q1 = LD2(rowB + 16), q2 = LD2(rowB + 32);
                    PROW(0, q0, q1, q2);
                }
                {   // dy=-2 : p5..9
                    const ulonglong2 q0 = LD2(rowB + 320), q1 = LD2(rowB + 336), q2 = LD2(rowB + 352);
                    PROW(5, q0, q1, q2);
                }
                {   // dy=0 : p10..16 (dx -4,-2,-1,0,1,2,4) + own-pixel sq
                    const ulonglong2 q0 = LD2(rowB + 640), q1 = LD2(rowB + 656), q2 = LD2(rowB + 672);
                    F2(sqML, q1.x, q1.x); F2(sqMH, q1.y, q1.y);
                    F2(pL[10], cvL, q0.x); F2(pH[10], cvH, q0.y);
                    F2(pL[11], cvL, q0.y); F2(pH[11], cvH, q1.x);
                    const u64 P34 = PK(HIW(q0.y), LOW(q1.x));
                    const u64 P56 = PK(HIW(q1.x), LOW(q1.y));
                    const u64 P78 = PK(HIW(q1.y), LOW(q2.x));
                    F2(pL[12], cvL, P34);  F2(pH[12], cvH, P56);
                    F2(pL[13], cvL, q1.x); F2(pH[13], cvH, q1.y);
                    F2(pL[14], cvL, P56);  F2(pH[14], cvH, P78);
                    F2(pL[15], cvL, q1.y); F2(pH[15], cvH, q2.x);
                    F2(pL[16], cvL, q2.x); F2(pH[16], cvH, q2.y);
                }
            }
        } else {
            #pragma unroll
            for (int cc = 0; cc < CHUNK; cc++) {
                const char* secB = pbuf + cc * PSEC;
                const char* rowB = secB + rowOff;
                const ulonglong2 CV = LD2(cbuf + cc * 2048 + cvOff);
                const u64 cvL = CV.x, cvH = CV.y;
                F2(ssqL, cvL, cvL); F2(ssqH, cvH, cvH);
                if (doFB) {
                    const ulonglong2 SQ = LD2(secB + fbOff);
                    F2(sqFL, SQ.x, SQ.x); F2(sqFH, SQ.y, SQ.y);
                }
                {   // dy=-1 : p0..2
                    const u64 a1 = LD1(rowB + 488);
                    const ulonglong2 q1 = LD2(rowB + 496);
                    const u64 a4 = LD1(rowB + 512);
                    PMID(0, a1, q1, a4);
                }
                {   // dy=+1 : p3..5
                    const u64 a1 = LD1(rowB + 808);
                    const ulonglong2 q1 = LD2(rowB + 816);
                    const u64 a4 = LD1(rowB + 832);
                    PMID(3, a1, q1, a4);
                }
                {   // dy=+2 : p6..10
                    const ulonglong2 q0 = LD2(rowB + 960), q1 = LD2(rowB + 976), q2 = LD2(rowB + 992);
                    PROW(6, q0, q1, q2);
                }
                {   // dy=+4 : p11..15
                    const ulonglong2 q0 = LD2(rowB + 1280), q1 = LD2(rowB + 1296), q2 = LD2(rowB + 1312);
                    PROW(11, q0, q1, q2);
                }
            }
        }
        bC = (bC == 2) ? 0 : bC + 1;
    }

    // ---- epilogue: inverse prev norms into sspInv ----
    {
        float* ssp = (float*)(smem + SM_SSP);
        if (wg == 0) {    // interior slots from register sq
            const float a = FL(sqML), b = FH(sqML), c = FL(sqMH), d = FH(sqMH);
            float4 r;
            r.x = a > 0.f ? rsqrtf(a) : 0.f;
            r.y = b > 0.f ? rsqrtf(b) : 0.f;
            r.z = c > 0.f ? rsqrtf(c) : 0.f;
            r.w = d > 0.f ? rsqrtf(d) : 0.f;
            ((float4*)ssp)[(ty + 4) * 10 + g + 1] = r;
        }
        if (doFB) {       // boundary slots
            const float a = FL(sqFL), b = FH(sqFL), c = FL(sqFH), d = FH(sqFH);
            float4 r;
            r.x = a > 0.f ? rsqrtf(a) : 0.f;
            r.y = b > 0.f ? rsqrtf(b) : 0.f;
            r.z = c > 0.f ? rsqrtf(c) : 0.f;
            r.w = d > 0.f ? rsqrtf(d) : 0.f;
            ((float4*)ssp)[fbSlot] = r;
        }
    }
    __syncthreads();

    const float ic0 = rsqrtf(FL(ssqL));
    const float ic1 = rsqrtf(FH(ssqL));
    const float ic2 = rsqrtf(FL(ssqH));
    const float ic3 = rsqrtf(FH(ssqH));
    const u64 invL = PK(__float_as_uint(ic0), __float_as_uint(ic1));
    const u64 invH = PK(__float_as_uint(ic2), __float_as_uint(ic3));

    const char* srow = smem + SM_SSP + rowOff;
    char* outPix = (char*)(out + ((size_t)bb * 33 * HH + (y0 + ty)) * WW + x0 + tx4);

#define ESTP(OPL, PI, BL, BH) do { \
    ulonglong2 _r; \
    _r.x = M2(M2(pL[PI], invL), (BL)); \
    _r.y = M2(M2(pH[PI], invH), (BH)); \
    *(ulonglong2*)(outPix + (size_t)(OPL) * (PLANE * 4)) = _r; } while (0)

#define EROWF(ROFF, OPL, PI) do { \
    const ulonglong2 q0 = LD2(srow + (ROFF)), q1 = LD2(srow + (ROFF) + 16), \
                     q2 = LD2(srow + (ROFF) + 32); \
    ESTP(OPL + 0, PI + 0, q0.x, q0.y); \
    ESTP(OPL + 1, PI + 1, q0.y, q1.x); \
    ESTP(OPL + 2, PI + 2, q1.x, q1.y); \
    ESTP(OPL + 3, PI + 3, q1.y, q2.x); \
    ESTP(OPL + 4, PI + 4, q2.x, q2.y); } while (0)

#define EMID(ROFF, OPL, PI) do { \
    const u64 a1 = LD1(srow + (ROFF) - 8); \
    const ulonglong2 q1 = LD2(srow + (ROFF)); \
    const u64 a4 = LD1(srow + (ROFF) + 16); \
    const u64 P34 = PK(HIW(a1), LOW(q1.x)); \
    const u64 P56 = PK(HIW(q1.x), LOW(q1.y)); \
    const u64 P78 = PK(HIW(q1.y), LOW(a4)); \
    ESTP(OPL + 0, PI + 0, P34, P56); \
    ESTP(OPL + 1, PI + 1, q1.x, q1.y); \
    ESTP(OPL + 2, PI + 2, P56, P78); } while (0)

    if (wg == 0) {
        EROWF(0, 0, 0);       // dy=-4: o0..4
        EROWF(320, 5, 5);     // dy=-2: o5..9
        {                     // dy=0: o13..19 (p10..16)
            const ulonglong2 q0 = LD2(srow + 640), q1 = LD2(srow + 656), q2 = LD2(srow + 672);
            ESTP(13, 10, q0.x, q0.y);
            ESTP(14, 11, q0.y, q1.x);
            const u64 P34 = PK(HIW(q0.y), LOW(q1.x));
            const u64 P56 = PK(HIW(q1.x), LOW(q1.y));
            const u64 P78 = PK(HIW(q1.y), LOW(q2.x));
            ESTP(15, 12, P34, P56);
            ESTP(16, 13, q1.x, q1.y);
            ESTP(17, 14, P56, P78);
            ESTP(18, 15, q1.y, q2.x);
            ESTP(19, 16, q2.x, q2.y);
        }
    } else {
        EMID(496, 10, 0);     // dy=-1: o10..12
        EMID(816, 20, 3);     // dy=+1: o20..22
        EROWF(960, 23, 6);    // dy=+2: o23..27
        EROWF(1280, 28, 11);  // dy=+4: o28..32
    }
}

extern "C" void kernel_launch(void* const* d_in, const int* in_sizes, int n_in,
                              void* d_out, int out_size)
{
    const float* curr = (const float*)d_in[0];
    const float* prev = (const float*)d_in[1];
    float* out = (float*)d_out;

    cudaFuncSetAttribute(corr_kernel, cudaFuncAttributeMaxDynamicSharedMemorySize, SMEM_BYTES);

    dim3 grid(WW / TILE_W, HH / TILE_H, BB);   // 6 x 8 x 8 = 384 blocks
    corr_kernel<<<grid, NT, SMEM_BYTES>>>(curr, prev, out);
}